// round 1
// baseline (speedup 1.0000x reference)
#include <cuda_runtime.h>

// Problem constants
#define CC   256          // channels
#define MM   2024         // memory slots
#define NPIX 32768        // B*H*W = 8*64*64
#define CHID 64           // hidden dim of gate MLP
#define HH   64
#define WW   64
#define BBATCH 8
#define KT   32           // memory rows per tile
#define PT   32           // pixels per block
#define NT   ((MM + KT - 1) / KT)   // 64 tiles
#define ROWP 260          // padded smem row stride (floats)
#define INV_TEMP (1.0f/0.03f)

// Scratch (static device globals; no dynamic allocation allowed)
__device__ float g_fgn[MM * CC];            // normalized fg memory
__device__ float g_bgn[MM * CC];            // normalized bg memory
__device__ float g_xn[(size_t)NPIX * CC];   // normalized pixel features [N,C]
__device__ float g_gfg[NPIX];
__device__ float g_gbg[NPIX];

// ---------------------------------------------------------------------------
// K1: L2-normalize the memory banks. One warp per row.
// ---------------------------------------------------------------------------
__global__ void norm_mem_kernel(const float* __restrict__ fg,
                                const float* __restrict__ bg) {
    int warp = (blockIdx.x * blockDim.x + threadIdx.x) >> 5;
    int lane = threadIdx.x & 31;
    if (warp >= 2 * MM) return;
    const float* src = (warp < MM) ? fg : bg;
    float* dst       = (warp < MM) ? g_fgn : g_bgn;
    int row          = (warp < MM) ? warp : warp - MM;

    const float4* s4 = (const float4*)(src + (size_t)row * CC);
    float4 v0 = s4[lane];
    float4 v1 = s4[lane + 32];
    float ss = v0.x*v0.x + v0.y*v0.y + v0.z*v0.z + v0.w*v0.w
             + v1.x*v1.x + v1.y*v1.y + v1.z*v1.z + v1.w*v1.w;
    #pragma unroll
    for (int o = 16; o; o >>= 1) ss += __shfl_xor_sync(0xffffffffu, ss, o);
    float inv = 1.0f / fmaxf(sqrtf(ss), 1e-12f);
    v0.x *= inv; v0.y *= inv; v0.z *= inv; v0.w *= inv;
    v1.x *= inv; v1.y *= inv; v1.z *= inv; v1.w *= inv;
    float4* d4 = (float4*)(dst + (size_t)row * CC);
    d4[lane]      = v0;
    d4[lane + 32] = v1;
}

// ---------------------------------------------------------------------------
// K2: transpose feats [B,C,H,W] -> xn [N,C], L2-normalized per pixel.
// One block per (b,h) row of 64 pixels.
// ---------------------------------------------------------------------------
__global__ void xn_kernel(const float* __restrict__ feats) {
    __shared__ float part[4][64];
    __shared__ float sinv[64];

    int bh = blockIdx.x;           // 0..511
    int b  = bh >> 6;
    int h  = bh & 63;
    int tid = threadIdx.x;

    // Phase A: sum of squares per pixel (coalesced reads along w)
    int w  = tid & 63;
    int cg = tid >> 6;             // 0..3
    float ps = 0.f;
    for (int c = cg; c < CC; c += 4) {
        float v = feats[(((size_t)b * CC + c) * HH + h) * WW + w];
        ps = fmaf(v, v, ps);
    }
    part[cg][w] = ps;
    __syncthreads();
    if (tid < 64) {
        float s = part[0][tid] + part[1][tid] + part[2][tid] + part[3][tid];
        sinv[tid] = 1.0f / fmaxf(sqrtf(s), 1e-12f);
    }
    __syncthreads();

    // Phase B: write xn coalesced along c (reads strided; cheap kernel)
    int nbase = bh * 64;
    for (int i = tid; i < CC * 64; i += 256) {
        int ww = i >> 8;           // pixel within row
        int c  = i & 255;
        float v = feats[(((size_t)b * CC + c) * HH + h) * WW + ww];
        g_xn[(size_t)(nbase + ww) * CC + c] = v * sinv[ww];
    }
}

// ---------------------------------------------------------------------------
// K3: gate MLPs: g = sigmoid(relu(xn@w1+b1)@w2+b2). One warp per pixel.
// ---------------------------------------------------------------------------
__global__ void gate_kernel(const float* __restrict__ w1f, const float* __restrict__ b1f,
                            const float* __restrict__ w2f, const float* __restrict__ b2f,
                            const float* __restrict__ w1b, const float* __restrict__ b1b,
                            const float* __restrict__ w2b, const float* __restrict__ b2b) {
    __shared__ float xs[8][CC];
    int n0  = blockIdx.x * 8;
    int tid = threadIdx.x;
    for (int i = tid; i < 8 * CC; i += 256)
        ((float*)xs)[i] = g_xn[(size_t)n0 * CC + i];
    __syncthreads();

    int wp = tid >> 5, lane = tid & 31;
    int n = n0 + wp;

    // fg gate
    {
        float a0 = b1f[lane], a1 = b1f[lane + 32];
        for (int c = 0; c < CC; c++) {
            float xv = xs[wp][c];
            a0 = fmaf(xv, w1f[c * CHID + lane],      a0);
            a1 = fmaf(xv, w1f[c * CHID + lane + 32], a1);
        }
        a0 = fmaxf(a0, 0.f); a1 = fmaxf(a1, 0.f);
        float s = a0 * w2f[lane] + a1 * w2f[lane + 32];
        #pragma unroll
        for (int o = 16; o; o >>= 1) s += __shfl_xor_sync(0xffffffffu, s, o);
        if (lane == 0) g_gfg[n] = 1.0f / (1.0f + __expf(-(s + b2f[0])));
    }
    // bg gate
    {
        float a0 = b1b[lane], a1 = b1b[lane + 32];
        for (int c = 0; c < CC; c++) {
            float xv = xs[wp][c];
            a0 = fmaf(xv, w1b[c * CHID + lane],      a0);
            a1 = fmaf(xv, w1b[c * CHID + lane + 32], a1);
        }
        a0 = fmaxf(a0, 0.f); a1 = fmaxf(a1, 0.f);
        float s = a0 * w2b[lane] + a1 * w2b[lane + 32];
        #pragma unroll
        for (int o = 16; o; o >>= 1) s += __shfl_xor_sync(0xffffffffu, s, o);
        if (lane == 0) g_gbg[n] = 1.0f / (1.0f + __expf(-(s + b2b[0])));
    }
}

// ---------------------------------------------------------------------------
// K4: fused dual softmax-attention (flash-style, online softmax).
// Block = 128 threads, 32 pixels, loops over 64 tiles of 32 memory rows.
// Roles:
//  logits: warp g handles pixels [g*8, g*8+8); lane = memory row within tile
//  acc:    thread (pa = tid&31, cb = tid>>5) owns pixel pa, channels cb*64..+63
// ---------------------------------------------------------------------------
__global__ __launch_bounds__(128, 2) void attn_kernel(float* __restrict__ out) {
    extern __shared__ float sm[];
    float* xn_s    = sm;                      // PT*ROWP
    float* mem_s   = xn_s + PT * ROWP;        // KT*ROWP
    float* probs   = mem_s + KT * ROWP;       // PT*33
    float* alpha_s = probs + PT * 33;         // PT
    float* lf_s    = alpha_s + PT;            // PT
    float* lb_s    = lf_s + PT;               // PT

    const int tid   = threadIdx.x;
    const int nbase = blockIdx.x * PT;
    const int b  = nbase >> 12;
    const int h  = (nbase >> 6) & 63;
    const int w0 = nbase & 63;

    // stage normalized pixel rows
    for (int i = tid; i < PT * CC; i += 128) {
        int p = i >> 8, c = i & 255;
        xn_s[p * ROWP + c] = g_xn[(size_t)nbase * CC + i];
    }

    const int lk = tid & 31;   // logits: memory row lane
    const int g  = tid >> 5;   // logits: pixel group (warp id)
    const int pa = tid & 31;   // acc: pixel
    const int cb = tid >> 5;   // acc: channel block

    float4 accf[16], accb[16];

    auto run_pass = [&](const float* __restrict__ src, float4 (&acc)[16],
                        float* l_out) {
        float m_run[8], l_run[8];
        #pragma unroll
        for (int j = 0; j < 8; j++) { m_run[j] = -1e30f; l_run[j] = 0.f; }
        #pragma unroll
        for (int i = 0; i < 16; i++) acc[i] = make_float4(0.f, 0.f, 0.f, 0.f);

        for (int t0 = 0; t0 < NT; t0++) {
            __syncthreads();   // prior acc step done with mem_s/probs (also covers xn_s staging)
            for (int i = tid; i < KT * CC; i += 128) {
                int r = i >> 8, c = i & 255;
                int mr = t0 * KT + r;
                mem_s[r * ROWP + c] = (mr < MM) ? src[(size_t)mr * CC + c] : 0.f;
            }
            __syncthreads();

            // ---- logits: 8 pixels x this lane's memory row ----
            float s8[8];
            #pragma unroll
            for (int j = 0; j < 8; j++) s8[j] = 0.f;
            const float4* mrow = (const float4*)(mem_s + lk * ROWP);
            #pragma unroll 4
            for (int c4 = 0; c4 < CC / 4; c4++) {
                float4 mv = mrow[c4];
                #pragma unroll
                for (int j = 0; j < 8; j++) {
                    float4 xv = ((const float4*)(xn_s + (g * 8 + j) * ROWP))[c4];
                    s8[j] = fmaf(mv.x, xv.x, s8[j]);
                    s8[j] = fmaf(mv.y, xv.y, s8[j]);
                    s8[j] = fmaf(mv.z, xv.z, s8[j]);
                    s8[j] = fmaf(mv.w, xv.w, s8[j]);
                }
            }
            const bool kvalid = (t0 * KT + lk) < MM;

            // ---- online softmax (per-pixel across the 32 lanes) ----
            #pragma unroll
            for (int j = 0; j < 8; j++) {
                float s = kvalid ? s8[j] * INV_TEMP : -1e30f;
                float mx = s;
                #pragma unroll
                for (int o = 16; o; o >>= 1)
                    mx = fmaxf(mx, __shfl_xor_sync(0xffffffffu, mx, o));
                float m_new = fmaxf(m_run[j], mx);
                float al = __expf(m_run[j] - m_new);
                float pv = __expf(s - m_new);
                float sum = pv;
                #pragma unroll
                for (int o = 16; o; o >>= 1)
                    sum += __shfl_xor_sync(0xffffffffu, sum, o);
                l_run[j] = l_run[j] * al + sum;
                m_run[j] = m_new;
                probs[(g * 8 + j) * 33 + lk] = pv;
                if (lk == 0) alpha_s[g * 8 + j] = al;
            }
            __syncthreads();

            // ---- accumulate: acc[pa][cb*64..] += probs[pa][:] @ mem_s ----
            float al = alpha_s[pa];
            const float* prow = probs + pa * 33;
            #pragma unroll
            for (int i = 0; i < 16; i++) {
                acc[i].x *= al; acc[i].y *= al; acc[i].z *= al; acc[i].w *= al;
            }
            #pragma unroll 2
            for (int k = 0; k < KT; k++) {
                float pk = prow[k];
                const float4* mr4 = (const float4*)(mem_s + k * ROWP) + cb * 16;
                #pragma unroll
                for (int i = 0; i < 16; i++) {
                    float4 mv = mr4[i];
                    acc[i].x = fmaf(pk, mv.x, acc[i].x);
                    acc[i].y = fmaf(pk, mv.y, acc[i].y);
                    acc[i].z = fmaf(pk, mv.z, acc[i].z);
                    acc[i].w = fmaf(pk, mv.w, acc[i].w);
                }
            }
        }
        if (lk == 0) {
            #pragma unroll
            for (int j = 0; j < 8; j++) l_out[g * 8 + j] = l_run[j];
        }
    };

    run_pass(g_fgn, accf, lf_s);
    run_pass(g_bgn, accb, lb_s);
    __syncthreads();

    // ---- epilogue: fused = xn + gfg*mem_fg - gbg*mem_bg, scatter to NCHW ----
    const float gf = g_gfg[nbase + pa];
    const float gb = g_gbg[nbase + pa];
    const float cf  = gf / lf_s[pa];
    const float cbg = gb / lb_s[pa];
    float* obase = out + (((size_t)b * CC) * HH + h) * WW + w0 + pa;
    #pragma unroll
    for (int i = 0; i < 16; i++) {
        float4 af = accf[i], ab = accb[i];
        int c0 = cb * 64 + i * 4;
        const float* xr = xn_s + pa * ROWP + c0;
        obase[(size_t)(c0 + 0) * (HH * WW)] = xr[0] + cf * af.x - cbg * ab.x;
        obase[(size_t)(c0 + 1) * (HH * WW)] = xr[1] + cf * af.y - cbg * ab.y;
        obase[(size_t)(c0 + 2) * (HH * WW)] = xr[2] + cf * af.z - cbg * ab.z;
        obase[(size_t)(c0 + 3) * (HH * WW)] = xr[3] + cf * af.w - cbg * ab.w;
    }
}

// ---------------------------------------------------------------------------
extern "C" void kernel_launch(void* const* d_in, const int* in_sizes, int n_in,
                              void* d_out, int out_size) {
    const float* feats = (const float*)d_in[0];
    const float* fgm   = (const float*)d_in[1];
    const float* bgm   = (const float*)d_in[2];
    const float* w1f   = (const float*)d_in[3];
    const float* b1f   = (const float*)d_in[4];
    const float* w2f   = (const float*)d_in[5];
    const float* b2f   = (const float*)d_in[6];
    const float* w1b   = (const float*)d_in[7];
    const float* b1b   = (const float*)d_in[8];
    const float* w2b   = (const float*)d_in[9];
    const float* b2b   = (const float*)d_in[10];
    float* out = (float*)d_out;

    const int smem_bytes = (PT * ROWP + KT * ROWP + PT * 33 + 3 * PT) * sizeof(float);
    cudaFuncSetAttribute(attn_kernel,
                         cudaFuncAttributeMaxDynamicSharedMemorySize, smem_bytes);

    norm_mem_kernel<<<(2 * MM + 7) / 8, 256>>>(fgm, bgm);
    xn_kernel<<<BBATCH * HH, 256>>>(feats);
    gate_kernel<<<NPIX / 8, 256>>>(w1f, b1f, w2f, b2f, w1b, b1b, w2b, b2b);
    attn_kernel<<<NPIX / PT, 128, smem_bytes>>>(out);
}

// round 2
// speedup vs baseline: 1.0009x; 1.0009x over previous
#include <cuda_runtime.h>

// Problem constants
#define CC   256          // channels
#define MM   2024         // memory slots
#define NPIX 32768        // B*H*W = 8*64*64
#define CHID 64           // hidden dim of gate MLP
#define HH   64
#define WW   64
#define BBATCH 8
#define KT   32           // memory rows per tile
#define PT   32           // pixels per block
#define NT   ((MM + KT - 1) / KT)   // 64 tiles
#define ROWP 260          // padded smem row stride (floats)
#define INV_TEMP (1.0f/0.03f)

// Scratch (static device globals; no dynamic allocation allowed)
__device__ float g_fgn[MM * CC];            // normalized fg memory
__device__ float g_bgn[MM * CC];            // normalized bg memory
__device__ float g_xn[(size_t)NPIX * CC];   // normalized pixel features [N,C]
__device__ float g_gfg[NPIX];
__device__ float g_gbg[NPIX];

// ---------------------------------------------------------------------------
// K1: L2-normalize the memory banks. One warp per row.
// ---------------------------------------------------------------------------
__global__ void norm_mem_kernel(const float* __restrict__ fg,
                                const float* __restrict__ bg) {
    int warp = (blockIdx.x * blockDim.x + threadIdx.x) >> 5;
    int lane = threadIdx.x & 31;
    if (warp >= 2 * MM) return;
    const float* src = (warp < MM) ? fg : bg;
    float* dst       = (warp < MM) ? g_fgn : g_bgn;
    int row          = (warp < MM) ? warp : warp - MM;

    const float4* s4 = (const float4*)(src + (size_t)row * CC);
    float4 v0 = s4[lane];
    float4 v1 = s4[lane + 32];
    float ss = v0.x*v0.x + v0.y*v0.y + v0.z*v0.z + v0.w*v0.w
             + v1.x*v1.x + v1.y*v1.y + v1.z*v1.z + v1.w*v1.w;
    #pragma unroll
    for (int o = 16; o; o >>= 1) ss += __shfl_xor_sync(0xffffffffu, ss, o);
    float inv = 1.0f / fmaxf(sqrtf(ss), 1e-12f);
    v0.x *= inv; v0.y *= inv; v0.z *= inv; v0.w *= inv;
    v1.x *= inv; v1.y *= inv; v1.z *= inv; v1.w *= inv;
    float4* d4 = (float4*)(dst + (size_t)row * CC);
    d4[lane]      = v0;
    d4[lane + 32] = v1;
}

// ---------------------------------------------------------------------------
// K2: transpose feats [B,C,H,W] -> xn [N,C], L2-normalized per pixel.
// One block per (b,h) row of 64 pixels.
// ---------------------------------------------------------------------------
__global__ void xn_kernel(const float* __restrict__ feats) {
    __shared__ float part[4][64];
    __shared__ float sinv[64];

    int bh = blockIdx.x;           // 0..511
    int b  = bh >> 6;
    int h  = bh & 63;
    int tid = threadIdx.x;

    // Phase A: sum of squares per pixel (coalesced reads along w)
    int w  = tid & 63;
    int cg = tid >> 6;             // 0..3
    float ps = 0.f;
    for (int c = cg; c < CC; c += 4) {
        float v = feats[(((size_t)b * CC + c) * HH + h) * WW + w];
        ps = fmaf(v, v, ps);
    }
    part[cg][w] = ps;
    __syncthreads();
    if (tid < 64) {
        float s = part[0][tid] + part[1][tid] + part[2][tid] + part[3][tid];
        sinv[tid] = 1.0f / fmaxf(sqrtf(s), 1e-12f);
    }
    __syncthreads();

    // Phase B: write xn coalesced along c (reads strided; cheap kernel)
    int nbase = bh * 64;
    for (int i = tid; i < CC * 64; i += 256) {
        int ww = i >> 8;           // pixel within row
        int c  = i & 255;
        float v = feats[(((size_t)b * CC + c) * HH + h) * WW + ww];
        g_xn[(size_t)(nbase + ww) * CC + c] = v * sinv[ww];
    }
}

// ---------------------------------------------------------------------------
// K3: gate MLPs: g = sigmoid(relu(xn@w1+b1)@w2+b2). One warp per pixel.
// ---------------------------------------------------------------------------
__global__ void gate_kernel(const float* __restrict__ w1f, const float* __restrict__ b1f,
                            const float* __restrict__ w2f, const float* __restrict__ b2f,
                            const float* __restrict__ w1b, const float* __restrict__ b1b,
                            const float* __restrict__ w2b, const float* __restrict__ b2b) {
    __shared__ float xs[8][CC];
    int n0  = blockIdx.x * 8;
    int tid = threadIdx.x;
    for (int i = tid; i < 8 * CC; i += 256)
        ((float*)xs)[i] = g_xn[(size_t)n0 * CC + i];
    __syncthreads();

    int wp = tid >> 5, lane = tid & 31;
    int n = n0 + wp;

    // fg gate
    {
        float a0 = b1f[lane], a1 = b1f[lane + 32];
        for (int c = 0; c < CC; c++) {
            float xv = xs[wp][c];
            a0 = fmaf(xv, w1f[c * CHID + lane],      a0);
            a1 = fmaf(xv, w1f[c * CHID + lane + 32], a1);
        }
        a0 = fmaxf(a0, 0.f); a1 = fmaxf(a1, 0.f);
        float s = a0 * w2f[lane] + a1 * w2f[lane + 32];
        #pragma unroll
        for (int o = 16; o; o >>= 1) s += __shfl_xor_sync(0xffffffffu, s, o);
        if (lane == 0) g_gfg[n] = 1.0f / (1.0f + __expf(-(s + b2f[0])));
    }
    // bg gate
    {
        float a0 = b1b[lane], a1 = b1b[lane + 32];
        for (int c = 0; c < CC; c++) {
            float xv = xs[wp][c];
            a0 = fmaf(xv, w1b[c * CHID + lane],      a0);
            a1 = fmaf(xv, w1b[c * CHID + lane + 32], a1);
        }
        a0 = fmaxf(a0, 0.f); a1 = fmaxf(a1, 0.f);
        float s = a0 * w2b[lane] + a1 * w2b[lane + 32];
        #pragma unroll
        for (int o = 16; o; o >>= 1) s += __shfl_xor_sync(0xffffffffu, s, o);
        if (lane == 0) g_gbg[n] = 1.0f / (1.0f + __expf(-(s + b2b[0])));
    }
}

// ---------------------------------------------------------------------------
// K4: fused dual softmax-attention (flash-style, online softmax).
// Block = 128 threads, 32 pixels, loops over 64 tiles of 32 memory rows.
// Roles:
//  logits: warp g handles pixels [g*8, g*8+8); lane = memory row within tile
//  acc:    thread (pa = tid&31, cb = tid>>5) owns pixel pa, channels cb*64..+63
// ---------------------------------------------------------------------------
__global__ __launch_bounds__(128, 2) void attn_kernel(float* __restrict__ out) {
    extern __shared__ float sm[];
    float* xn_s    = sm;                      // PT*ROWP
    float* mem_s   = xn_s + PT * ROWP;        // KT*ROWP
    float* probs   = mem_s + KT * ROWP;       // PT*33
    float* alpha_s = probs + PT * 33;         // PT
    float* lf_s    = alpha_s + PT;            // PT
    float* lb_s    = lf_s + PT;               // PT

    const int tid   = threadIdx.x;
    const int nbase = blockIdx.x * PT;
    const int b  = nbase >> 12;
    const int h  = (nbase >> 6) & 63;
    const int w0 = nbase & 63;

    // stage normalized pixel rows
    for (int i = tid; i < PT * CC; i += 128) {
        int p = i >> 8, c = i & 255;
        xn_s[p * ROWP + c] = g_xn[(size_t)nbase * CC + i];
    }

    const int lk = tid & 31;   // logits: memory row lane
    const int g  = tid >> 5;   // logits: pixel group (warp id)
    const int pa = tid & 31;   // acc: pixel
    const int cb = tid >> 5;   // acc: channel block

    float4 accf[16], accb[16];

    auto run_pass = [&](const float* __restrict__ src, float4 (&acc)[16],
                        float* l_out) {
        float m_run[8], l_run[8];
        #pragma unroll
        for (int j = 0; j < 8; j++) { m_run[j] = -1e30f; l_run[j] = 0.f; }
        #pragma unroll
        for (int i = 0; i < 16; i++) acc[i] = make_float4(0.f, 0.f, 0.f, 0.f);

        for (int t0 = 0; t0 < NT; t0++) {
            __syncthreads();   // prior acc step done with mem_s/probs (also covers xn_s staging)
            for (int i = tid; i < KT * CC; i += 128) {
                int r = i >> 8, c = i & 255;
                int mr = t0 * KT + r;
                mem_s[r * ROWP + c] = (mr < MM) ? src[(size_t)mr * CC + c] : 0.f;
            }
            __syncthreads();

            // ---- logits: 8 pixels x this lane's memory row ----
            float s8[8];
            #pragma unroll
            for (int j = 0; j < 8; j++) s8[j] = 0.f;
            const float4* mrow = (const float4*)(mem_s + lk * ROWP);
            #pragma unroll 4
            for (int c4 = 0; c4 < CC / 4; c4++) {
                float4 mv = mrow[c4];
                #pragma unroll
                for (int j = 0; j < 8; j++) {
                    float4 xv = ((const float4*)(xn_s + (g * 8 + j) * ROWP))[c4];
                    s8[j] = fmaf(mv.x, xv.x, s8[j]);
                    s8[j] = fmaf(mv.y, xv.y, s8[j]);
                    s8[j] = fmaf(mv.z, xv.z, s8[j]);
                    s8[j] = fmaf(mv.w, xv.w, s8[j]);
                }
            }
            const bool kvalid = (t0 * KT + lk) < MM;

            // ---- online softmax (per-pixel across the 32 lanes) ----
            #pragma unroll
            for (int j = 0; j < 8; j++) {
                float s = kvalid ? s8[j] * INV_TEMP : -1e30f;
                float mx = s;
                #pragma unroll
                for (int o = 16; o; o >>= 1)
                    mx = fmaxf(mx, __shfl_xor_sync(0xffffffffu, mx, o));
                float m_new = fmaxf(m_run[j], mx);
                float al = __expf(m_run[j] - m_new);
                float pv = __expf(s - m_new);
                float sum = pv;
                #pragma unroll
                for (int o = 16; o; o >>= 1)
                    sum += __shfl_xor_sync(0xffffffffu, sum, o);
                l_run[j] = l_run[j] * al + sum;
                m_run[j] = m_new;
                probs[(g * 8 + j) * 33 + lk] = pv;
                if (lk == 0) alpha_s[g * 8 + j] = al;
            }
            __syncthreads();

            // ---- accumulate: acc[pa][cb*64..] += probs[pa][:] @ mem_s ----
            float al = alpha_s[pa];
            const float* prow = probs + pa * 33;
            #pragma unroll
            for (int i = 0; i < 16; i++) {
                acc[i].x *= al; acc[i].y *= al; acc[i].z *= al; acc[i].w *= al;
            }
            #pragma unroll 2
            for (int k = 0; k < KT; k++) {
                float pk = prow[k];
                const float4* mr4 = (const float4*)(mem_s + k * ROWP) + cb * 16;
                #pragma unroll
                for (int i = 0; i < 16; i++) {
                    float4 mv = mr4[i];
                    acc[i].x = fmaf(pk, mv.x, acc[i].x);
                    acc[i].y = fmaf(pk, mv.y, acc[i].y);
                    acc[i].z = fmaf(pk, mv.z, acc[i].z);
                    acc[i].w = fmaf(pk, mv.w, acc[i].w);
                }
            }
        }
        if (lk == 0) {
            #pragma unroll
            for (int j = 0; j < 8; j++) l_out[g * 8 + j] = l_run[j];
        }
    };

    run_pass(g_fgn, accf, lf_s);
    run_pass(g_bgn, accb, lb_s);
    __syncthreads();

    // ---- epilogue: fused = xn + gfg*mem_fg - gbg*mem_bg, scatter to NCHW ----
    const float gf = g_gfg[nbase + pa];
    const float gb = g_gbg[nbase + pa];
    const float cf  = gf / lf_s[pa];
    const float cbg = gb / lb_s[pa];
    float* obase = out + (((size_t)b * CC) * HH + h) * WW + w0 + pa;
    #pragma unroll
    for (int i = 0; i < 16; i++) {
        float4 af = accf[i], ab = accb[i];
        int c0 = cb * 64 + i * 4;
        const float* xr = xn_s + pa * ROWP + c0;
        obase[(size_t)(c0 + 0) * (HH * WW)] = xr[0] + cf * af.x - cbg * ab.x;
        obase[(size_t)(c0 + 1) * (HH * WW)] = xr[1] + cf * af.y - cbg * ab.y;
        obase[(size_t)(c0 + 2) * (HH * WW)] = xr[2] + cf * af.z - cbg * ab.z;
        obase[(size_t)(c0 + 3) * (HH * WW)] = xr[3] + cf * af.w - cbg * ab.w;
    }
}

// ---------------------------------------------------------------------------
extern "C" void kernel_launch(void* const* d_in, const int* in_sizes, int n_in,
                              void* d_out, int out_size) {
    const float* feats = (const float*)d_in[0];
    const float* fgm   = (const float*)d_in[1];
    const float* bgm   = (const float*)d_in[2];
    const float* w1f   = (const float*)d_in[3];
    const float* b1f   = (const float*)d_in[4];
    const float* w2f   = (const float*)d_in[5];
    const float* b2f   = (const float*)d_in[6];
    const float* w1b   = (const float*)d_in[7];
    const float* b1b   = (const float*)d_in[8];
    const float* w2b   = (const float*)d_in[9];
    const float* b2b   = (const float*)d_in[10];
    float* out = (float*)d_out;

    const int smem_bytes = (PT * ROWP + KT * ROWP + PT * 33 + 3 * PT) * sizeof(float);
    cudaFuncSetAttribute(attn_kernel,
                         cudaFuncAttributeMaxDynamicSharedMemorySize, smem_bytes);

    norm_mem_kernel<<<(2 * MM + 7) / 8, 256>>>(fgm, bgm);
    xn_kernel<<<BBATCH * HH, 256>>>(feats);
    gate_kernel<<<NPIX / 8, 256>>>(w1f, b1f, w2f, b2f, w1b, b1b, w2b, b2b);
    attn_kernel<<<NPIX / PT, 128, smem_bytes>>>(out);
}

// round 7
// speedup vs baseline: 5.1270x; 5.1225x over previous
#include <cuda_runtime.h>
#include <cstdint>

#define CC   256
#define MM   2024
#define NPIX 32768
#define CHID 64
#define PT   64
#define KT   32
#define NTILE 64          // tiles per bank
#define NTT  128          // total (fg+bg)
#define INV_TEMP (1.0f/0.03f)

// dynamic smem byte offsets
#define QF_OFF  0         // 65536: Q fragments
#define TB_OFF  65536     // 2 x 65536: tile fragment buffers (T1F 32KB + T2F 32KB each)
#define TB_SZ   65536
#define PF_OFF  196608    // 8192: P fragments
#define LSM_OFF 204800    // 2*64 floats
#define SMEM_DYN 205312

// ---------------- global scratch ----------------
__device__ float g_xn[(size_t)NPIX*CC];
__device__ float g_gfg[NPIX];
__device__ float g_gbg[NPIX];
__device__ __align__(16) float g_qf[(size_t)NPIX*CC];        // 64KB per CTA, frag-major
__device__ __align__(16) float g_timg[(size_t)NTT*16384];    // 128 tiles * 64KB frag-major

// ---------------- helpers ----------------
__device__ __forceinline__ uint32_t s2u(const void* p){
    uint32_t a;
    asm("{ .reg .u64 t; cvta.to.shared.u64 t, %1; cvt.u32.u64 %0, t; }" : "=r"(a) : "l"(p));
    return a;
}
__device__ __forceinline__ float tf32r(float x){
    asm("cvt.rna.tf32.f32 %0, %1;" : "=f"(x) : "f"(x));
    return x;
}
__device__ __forceinline__ void mbar_init(uint32_t m, uint32_t c){
    asm volatile("mbarrier.init.shared.b64 [%0], %1;" :: "r"(m), "r"(c) : "memory");
}
__device__ __forceinline__ void mbar_tx(uint32_t m, uint32_t b){
    asm volatile("mbarrier.arrive.expect_tx.shared.b64 _, [%0], %1;" :: "r"(m), "r"(b) : "memory");
}
__device__ __forceinline__ void mbar_wait(uint32_t m, uint32_t ph){
    asm volatile(
        "{\n\t.reg .pred P;\n\t"
        "W_%=:\n\t"
        "mbarrier.try_wait.parity.acquire.cta.shared::cta.b64 P, [%0], %1, 0x989680;\n\t"
        "@P bra D_%=;\n\tbra W_%=;\n\tD_%=:\n\t}"
        :: "r"(m), "r"(ph) : "memory");
}
__device__ __forceinline__ void bulk_g2s(uint32_t dst, const void* src, uint32_t bytes, uint32_t mbar){
    asm volatile("cp.async.bulk.shared::cluster.global.mbarrier::complete_tx::bytes [%0], [%1], %2, [%3];"
        :: "r"(dst), "l"(src), "r"(bytes), "r"(mbar) : "memory");
}
// m16n8k8 tf32 mma, D=C in place
__device__ __forceinline__ void mma8(float* d, uint4 a, uint2 b){
    asm volatile("mma.sync.aligned.m16n8k8.row.col.f32.tf32.tf32.f32 "
        "{%0,%1,%2,%3}, {%4,%5,%6,%7}, {%8,%9}, {%0,%1,%2,%3};"
        : "+f"(d[0]), "+f"(d[1]), "+f"(d[2]), "+f"(d[3])
        : "r"(a.x), "r"(a.y), "r"(a.z), "r"(a.w), "r"(b.x), "r"(b.y));
}

// ---------------------------------------------------------------------------
// P1: normalize memory rows, emit fragment-major tile images.
// Per 32-slot tile: T1F (GEMM1 B, k=channel): 4nt x 32ks x 32lane float2 (32KB)
//                   T2F (GEMM2 B, k=slot):   32nt x 4ks  x 32lane float2 (32KB)
// ---------------------------------------------------------------------------
__global__ void pack_mem_kernel(const float* __restrict__ fg, const float* __restrict__ bg){
    __shared__ float rows[KT][CC+4];
    int blk = blockIdx.x;                 // 0..127
    int bank = blk >> 6, tin = blk & 63;
    const float* src = bank ? bg : fg;
    int tid = threadIdx.x, wid = tid>>5, lane = tid&31;

    #pragma unroll
    for (int i = 0; i < 4; i++){
        int r = wid*4 + i;
        int slot = tin*KT + r;
        float4 v0 = make_float4(0.f,0.f,0.f,0.f), v1 = v0;
        if (slot < MM){
            const float4* s4 = (const float4*)(src + (size_t)slot*CC);
            v0 = s4[lane]; v1 = s4[lane+32];
            float ss = v0.x*v0.x+v0.y*v0.y+v0.z*v0.z+v0.w*v0.w
                     + v1.x*v1.x+v1.y*v1.y+v1.z*v1.z+v1.w*v1.w;
            #pragma unroll
            for (int o = 16; o; o >>= 1) ss += __shfl_xor_sync(0xffffffffu, ss, o);
            float inv = 1.0f / fmaxf(sqrtf(ss), 1e-12f);
            v0.x*=inv; v0.y*=inv; v0.z*=inv; v0.w*=inv;
            v1.x*=inv; v1.y*=inv; v1.z*=inv; v1.w*=inv;
        }
        float4* d = (float4*)&rows[r][0];
        d[lane] = v0; d[lane+32] = v1;
    }
    __syncthreads();

    float* out = g_timg + (size_t)blk * 16384;
    for (int idx = tid; idx < 4096; idx += 256){
        int nt = idx>>10, ks = (idx>>5)&31, ln = idx&31;
        int slot = nt*8 + (ln>>2), ch = ks*8 + (ln&3);
        float2 v = make_float2(tf32r(rows[slot][ch]), tf32r(rows[slot][ch+4]));
        *(float2*)(out + (size_t)idx*2) = v;
    }
    for (int idx = tid; idx < 4096; idx += 256){
        int nt2 = idx>>7, ks2 = (idx>>5)&3, ln = idx&31;
        int slot = ks2*8 + (ln&3), ch = nt2*8 + (ln>>2);
        float2 v = make_float2(tf32r(rows[slot][ch]), tf32r(rows[slot+4][ch]));
        *(float2*)(out + 8192 + (size_t)idx*2) = v;
    }
}

// ---------------------------------------------------------------------------
// P2: feats [B,C,H,W] -> g_xn [N,C] L2-normalized
// ---------------------------------------------------------------------------
__global__ void xn_kernel(const float* __restrict__ feats){
    __shared__ float part[4][64];
    __shared__ float sinv[64];
    int bh = blockIdx.x, b = bh >> 6, h = bh & 63;
    int tid = threadIdx.x;
    int w = tid & 63, cg = tid >> 6;
    float ps = 0.f;
    for (int c = cg; c < CC; c += 4){
        float v = feats[(((size_t)b*CC + c)*64 + h)*64 + w];
        ps = fmaf(v, v, ps);
    }
    part[cg][w] = ps;
    __syncthreads();
    if (tid < 64){
        float s = part[0][tid] + part[1][tid] + part[2][tid] + part[3][tid];
        sinv[tid] = 1.0f / fmaxf(sqrtf(s), 1e-12f);
    }
    __syncthreads();
    int nbase = bh * 64;
    for (int i = tid; i < CC*64; i += 256){
        int ww = i >> 8, c = i & 255;
        float v = feats[(((size_t)b*CC + c)*64 + h)*64 + ww] * sinv[ww];
        g_xn[(size_t)(nbase + ww)*CC + c] = v;
    }
}

// ---------------------------------------------------------------------------
// P3: Q fragments per CTA (tf32-rounded), frag-major 64KB
// ---------------------------------------------------------------------------
__global__ void qpack_kernel(){
    int cta = blockIdx.x, tid = threadIdx.x;
    const float* q = g_xn + (size_t)cta * PT * CC;
    float* out = g_qf + (size_t)cta * 16384;
    for (int idx = tid; idx < 4096; idx += 256){
        int mt = idx>>10, ks = (idx>>5)&31, ln = idx&31;
        int m = mt*16 + (ln>>2), k = ks*8 + (ln&3);
        float4 v;
        v.x = tf32r(q[(size_t)m*CC + k]);
        v.y = tf32r(q[(size_t)(m+8)*CC + k]);
        v.z = tf32r(q[(size_t)m*CC + k + 4]);
        v.w = tf32r(q[(size_t)(m+8)*CC + k + 4]);
        *(float4*)(out + (size_t)idx*4) = v;
    }
}

// ---------------------------------------------------------------------------
// P4: gate MLPs (one warp per pixel)
// ---------------------------------------------------------------------------
__global__ void gate_kernel(const float* __restrict__ w1f, const float* __restrict__ b1f,
                            const float* __restrict__ w2f, const float* __restrict__ b2f,
                            const float* __restrict__ w1b, const float* __restrict__ b1b,
                            const float* __restrict__ w2b, const float* __restrict__ b2b){
    __shared__ float xs[8][CC];
    int n0 = blockIdx.x * 8, tid = threadIdx.x;
    for (int i = tid; i < 8*CC; i += 256) ((float*)xs)[i] = g_xn[(size_t)n0*CC + i];
    __syncthreads();
    int wp = tid >> 5, lane = tid & 31, n = n0 + wp;
    {
        float a0 = b1f[lane], a1 = b1f[lane+32];
        for (int c = 0; c < CC; c++){
            float xv = xs[wp][c];
            a0 = fmaf(xv, w1f[c*CHID+lane], a0);
            a1 = fmaf(xv, w1f[c*CHID+lane+32], a1);
        }
        a0 = fmaxf(a0, 0.f); a1 = fmaxf(a1, 0.f);
        float s = a0*w2f[lane] + a1*w2f[lane+32];
        #pragma unroll
        for (int o = 16; o; o >>= 1) s += __shfl_xor_sync(0xffffffffu, s, o);
        if (lane == 0) g_gfg[n] = 1.0f / (1.0f + __expf(-(s + b2f[0])));
    }
    {
        float a0 = b1b[lane], a1 = b1b[lane+32];
        for (int c = 0; c < CC; c++){
            float xv = xs[wp][c];
            a0 = fmaf(xv, w1b[c*CHID+lane], a0);
            a1 = fmaf(xv, w1b[c*CHID+lane+32], a1);
        }
        a0 = fmaxf(a0, 0.f); a1 = fmaxf(a1, 0.f);
        float s = a0*w2b[lane] + a1*w2b[lane+32];
        #pragma unroll
        for (int o = 16; o; o >>= 1) s += __shfl_xor_sync(0xffffffffu, s, o);
        if (lane == 0) g_gbg[n] = 1.0f / (1.0f + __expf(-(s + b2b[0])));
    }
}

// ---------------------------------------------------------------------------
// P5: fused dual attention via mma.sync tf32.
// 256 thr = 8 warps. warp w: mt = w&3 (16 pixel rows), nh = w>>2 (n-half).
// GEMM1: S[64x32]: warp computes frags (mt, nt = 2nh, 2nh+1).
// GEMM2: O[64x256]: warp computes frags (mt, nt2 = 16nh .. 16nh+15).
// ---------------------------------------------------------------------------
__global__ __launch_bounds__(256, 1) void attn_kernel(float* __restrict__ out){
    extern __shared__ __align__(16) char sm[];
    __shared__ __align__(8) unsigned long long barsm[3];

    const int tid = threadIdx.x, wid = tid >> 5, lane = tid & 31;
    const int cta = blockIdx.x;
    const int mt = wid & 3, nh = wid >> 2;

    const uint32_t smb  = s2u(sm);
    float* QFf = (float*)(sm + QF_OFF);
    float* PF  = (float*)(sm + PF_OFF);
    float* LSM = (float*)(sm + LSM_OFF);
    const uint32_t qbar = s2u(barsm);
    const uint32_t fbar0 = qbar + 8, fbar1 = qbar + 16;

    if (tid == 0){ mbar_init(qbar,1); mbar_init(fbar0,1); mbar_init(fbar1,1); }
    if (tid < 128) LSM[tid] = 0.f;
    __syncthreads();
    if (tid == 0){
        mbar_tx(qbar, 65536);
        bulk_g2s(smb + QF_OFF, g_qf + (size_t)cta*16384, 65536, qbar);
        mbar_tx(fbar0, TB_SZ);
        bulk_g2s(smb + TB_OFF, g_timg, TB_SZ, fbar0);
        mbar_tx(fbar1, TB_SZ);
        bulk_g2s(smb + TB_OFF + TB_SZ, g_timg + 16384, TB_SZ, fbar1);
    }
    mbar_wait(qbar, 0);

    const int rA = mt*16 + (lane>>2);
    const int nA = cta*64 + rA, nB = nA + 8;

    for (int pass = 0; pass < 2; pass++){
        float accO[16][4];
        #pragma unroll
        for (int j = 0; j < 16; j++)
            accO[j][0] = accO[j][1] = accO[j][2] = accO[j][3] = 0.f;
        float lA = 0.f, lB = 0.f;

        for (int tt = 0; tt < NTILE; tt++){
            const int t = pass*NTILE + tt;
            const int buf = t & 1;
            float* TB = (float*)(sm + TB_OFF + buf*TB_SZ);
            mbar_wait(buf ? fbar1 : fbar0, (t >> 1) & 1);

            // ---- GEMM1 ----
            float accS[2][4] = {{0,0,0,0},{0,0,0,0}};
            const uint4* Aq = (const uint4*)QFf + mt*1024 + lane;        // stride 32 per ks
            const uint2* B0 = (const uint2*)TB + (nh*2)*1024 + lane;
            const uint2* B1 = (const uint2*)TB + (nh*2+1)*1024 + lane;
            #pragma unroll 4
            for (int ks = 0; ks < 32; ks++){
                uint4 a = Aq[ks*32];
                mma8(accS[0], a, B0[ks*32]);
                mma8(accS[1], a, B1[ks*32]);
            }

            // ---- S epilogue: exp, mask padding, tf32 round, lsum, PF store ----
            #pragma unroll
            for (int f = 0; f < 2; f++){
                const int nt = nh*2 + f;
                const bool maskf = (tt == NTILE-1) && (nt > 0);   // slots >= 2024
                #pragma unroll
                for (int c = 0; c < 4; c++){
                    float p = __expf(accS[f][c] * INV_TEMP);
                    if (maskf) p = 0.f;
                    p = tf32r(p);
                    if (c < 2) lA += p; else lB += p;
                    int colin = 2*(lane & 3) + (c & 1);
                    int comp  = ((colin >= 4) ? 2 : 0) + ((c >> 1) & 1);
                    int tp    = (lane & ~3) | (colin & 3);
                    PF[((mt*4 + nt)*32 + tp)*4 + comp] = p;
                }
            }
            __syncthreads();

            // ---- GEMM2 ----
            const uint2* B2 = (const uint2*)(TB + 8192) + (nh*16)*128 + lane;
            #pragma unroll
            for (int ks2 = 0; ks2 < 4; ks2++){
                uint4 a = *((const uint4*)PF + (mt*4 + ks2)*32 + lane);
                #pragma unroll
                for (int j = 0; j < 16; j++)
                    mma8(accO[j], a, B2[j*128 + ks2*32]);
            }
            __syncthreads();

            // prefetch t+2 into the buffer just released
            if (tid == 0 && t + 2 < NTT){
                uint32_t fb = buf ? fbar1 : fbar0;
                mbar_tx(fb, TB_SZ);
                bulk_g2s(smb + TB_OFF + buf*TB_SZ, g_timg + (size_t)(t+2)*16384, TB_SZ, fb);
            }
        }

        // ---- pass epilogue ----
        lA += __shfl_xor_sync(0xffffffffu, lA, 1);
        lA += __shfl_xor_sync(0xffffffffu, lA, 2);
        lB += __shfl_xor_sync(0xffffffffu, lB, 1);
        lB += __shfl_xor_sync(0xffffffffu, lB, 2);
        if ((lane & 3) == 0){
            atomicAdd(&LSM[pass*64 + rA], lA);
            atomicAdd(&LSM[pass*64 + rA + 8], lB);
        }
        __syncthreads();

        const float gA = pass ? g_gbg[nA] : g_gfg[nA];
        const float gB = pass ? g_gbg[nB] : g_gfg[nB];
        const float cA = gA / LSM[pass*64 + rA];
        const float cB = gB / LSM[pass*64 + rA + 8];
        const size_t baseA = ((size_t)(nA >> 12) * CC) * 4096 + (nA & 4095);
        const size_t baseB = baseA + 8;   // nB = nA+8, same b
        const float* xnA = g_xn + (size_t)nA*CC;
        const float* xnB = g_xn + (size_t)nB*CC;

        #pragma unroll
        for (int j = 0; j < 16; j++){
            int c0 = (nh*16 + j)*8 + 2*(lane & 3);
            size_t aA = baseA + (size_t)c0*4096;
            size_t aB = baseB + (size_t)c0*4096;
            if (pass == 0){
                out[aA]        = xnA[c0]   + cA*accO[j][0];
                out[aA + 4096] = xnA[c0+1] + cA*accO[j][1];
                out[aB]        = xnB[c0]   + cB*accO[j][2];
                out[aB + 4096] = xnB[c0+1] + cB*accO[j][3];
            } else {
                out[aA]        -= cA*accO[j][0];
                out[aA + 4096] -= cA*accO[j][1];
                out[aB]        -= cB*accO[j][2];
                out[aB + 4096] -= cB*accO[j][3];
            }
        }
    }
}

// ---------------------------------------------------------------------------
extern "C" void kernel_launch(void* const* d_in, const int* in_sizes, int n_in,
                              void* d_out, int out_size){
    const float* feats = (const float*)d_in[0];
    const float* fgm   = (const float*)d_in[1];
    const float* bgm   = (const float*)d_in[2];
    const float* w1f   = (const float*)d_in[3];
    const float* b1f   = (const float*)d_in[4];
    const float* w2f   = (const float*)d_in[5];
    const float* b2f   = (const float*)d_in[6];
    const float* w1b   = (const float*)d_in[7];
    const float* b1b   = (const float*)d_in[8];
    const float* w2b   = (const float*)d_in[9];
    const float* b2b   = (const float*)d_in[10];
    float* out = (float*)d_out;

    cudaFuncSetAttribute(attn_kernel, cudaFuncAttributeMaxDynamicSharedMemorySize, SMEM_DYN);

    pack_mem_kernel<<<128, 256>>>(fgm, bgm);
    xn_kernel<<<512, 256>>>(feats);
    qpack_kernel<<<NPIX / PT, 256>>>();
    gate_kernel<<<NPIX / 8, 256>>>(w1f, b1f, w2f, b2f, w1b, b1b, w2b, b2b);
    attn_kernel<<<NPIX / PT, 256, SMEM_DYN>>>(out);
}

// round 8
// speedup vs baseline: 6.1718x; 1.2038x over previous
#include <cuda_runtime.h>
#include <cstdint>

#define CC   256
#define MM   2024
#define NPIX 32768
#define CHID 64
#define PT   64
#define KT   32
#define NTILE 64          // tiles per bank
#define NTT  128          // total (fg+bg)
#define INV_TEMP (1.0f/0.03f)

// dynamic smem byte offsets (attn)
#define QF_OFF  0         // 65536: Q fragments
#define TB_OFF  65536     // 2 x 65536: tile fragment buffers (T1F 32KB + T2F 32KB each)
#define TB_SZ   65536
#define PF_OFF  196608    // 8192: P fragments
#define LSM_OFF 204800    // 2*64 floats
#define SMEM_DYN 205312

#define XN_SMEM (64*260*4)   // xn_kernel dynamic smem

// ---------------- global scratch ----------------
__device__ float g_xn[(size_t)NPIX*CC];
__device__ float g_gfg[NPIX];
__device__ float g_gbg[NPIX];
__device__ __align__(16) float g_qf[(size_t)NPIX*CC];        // frag-major Q, 64KB per 64-px CTA
__device__ __align__(16) float g_timg[(size_t)NTT*16384];    // 128 tiles * 64KB frag-major
__device__ __align__(16) float g_wf[16384];                  // w1 frag images (fg+bg)

// ---------------- helpers ----------------
__device__ __forceinline__ uint32_t s2u(const void* p){
    uint32_t a;
    asm("{ .reg .u64 t; cvta.to.shared.u64 t, %1; cvt.u32.u64 %0, t; }" : "=r"(a) : "l"(p));
    return a;
}
__device__ __forceinline__ float tf32r(float x){
    asm("cvt.rna.tf32.f32 %0, %1;" : "=f"(x) : "f"(x));
    return x;
}
__device__ __forceinline__ void mbar_init(uint32_t m, uint32_t c){
    asm volatile("mbarrier.init.shared.b64 [%0], %1;" :: "r"(m), "r"(c) : "memory");
}
__device__ __forceinline__ void mbar_tx(uint32_t m, uint32_t b){
    asm volatile("mbarrier.arrive.expect_tx.shared.b64 _, [%0], %1;" :: "r"(m), "r"(b) : "memory");
}
__device__ __forceinline__ void mbar_wait(uint32_t m, uint32_t ph){
    asm volatile(
        "{\n\t.reg .pred P;\n\t"
        "W_%=:\n\t"
        "mbarrier.try_wait.parity.acquire.cta.shared::cta.b64 P, [%0], %1, 0x989680;\n\t"
        "@P bra D_%=;\n\tbra W_%=;\n\tD_%=:\n\t}"
        :: "r"(m), "r"(ph) : "memory");
}
__device__ __forceinline__ void bulk_g2s(uint32_t dst, const void* src, uint32_t bytes, uint32_t mbar){
    asm volatile("cp.async.bulk.shared::cluster.global.mbarrier::complete_tx::bytes [%0], [%1], %2, [%3];"
        :: "r"(dst), "l"(src), "r"(bytes), "r"(mbar) : "memory");
}
__device__ __forceinline__ void mma8(float* d, uint4 a, uint2 b){
    asm volatile("mma.sync.aligned.m16n8k8.row.col.f32.tf32.tf32.f32 "
        "{%0,%1,%2,%3}, {%4,%5,%6,%7}, {%8,%9}, {%0,%1,%2,%3};"
        : "+f"(d[0]), "+f"(d[1]), "+f"(d[2]), "+f"(d[3])
        : "r"(a.x), "r"(a.y), "r"(a.z), "r"(a.w), "r"(b.x), "r"(b.y));
}

// ---------------------------------------------------------------------------
// P1: normalize memory rows, emit fragment-major tile images.
// T1F (GEMM1 B, k=channel): [4nt][32ks][32lane] float2 (32KB)
// T2F (GEMM2 B, k=slot):    [32nt][4ks][32lane]  float2 (32KB)
// ---------------------------------------------------------------------------
__global__ void pack_mem_kernel(const float* __restrict__ fg, const float* __restrict__ bg){
    __shared__ float rows[KT][CC+4];
    int blk = blockIdx.x;                 // 0..127
    int bank = blk >> 6, tin = blk & 63;
    const float* src = bank ? bg : fg;
    int tid = threadIdx.x, wid = tid>>5, lane = tid&31;

    #pragma unroll
    for (int i = 0; i < 4; i++){
        int r = wid*4 + i;
        int slot = tin*KT + r;
        float4 v0 = make_float4(0.f,0.f,0.f,0.f), v1 = v0;
        if (slot < MM){
            const float4* s4 = (const float4*)(src + (size_t)slot*CC);
            v0 = s4[lane]; v1 = s4[lane+32];
            float ss = v0.x*v0.x+v0.y*v0.y+v0.z*v0.z+v0.w*v0.w
                     + v1.x*v1.x+v1.y*v1.y+v1.z*v1.z+v1.w*v1.w;
            #pragma unroll
            for (int o = 16; o; o >>= 1) ss += __shfl_xor_sync(0xffffffffu, ss, o);
            float inv = 1.0f / fmaxf(sqrtf(ss), 1e-12f);
            v0.x*=inv; v0.y*=inv; v0.z*=inv; v0.w*=inv;
            v1.x*=inv; v1.y*=inv; v1.z*=inv; v1.w*=inv;
        }
        float4* d = (float4*)&rows[r][0];
        d[lane] = v0; d[lane+32] = v1;
    }
    __syncthreads();

    float* out = g_timg + (size_t)blk * 16384;
    for (int idx = tid; idx < 4096; idx += 256){
        int nt = idx>>10, ks = (idx>>5)&31, ln = idx&31;
        int slot = nt*8 + (ln>>2), ch = ks*8 + (ln&3);
        float2 v = make_float2(tf32r(rows[slot][ch]), tf32r(rows[slot][ch+4]));
        *(float2*)(out + (size_t)idx*2) = v;
    }
    for (int idx = tid; idx < 4096; idx += 256){
        int nt2 = idx>>7, ks2 = (idx>>5)&3, ln = idx&31;
        int slot = ks2*8 + (ln&3), ch = nt2*8 + (ln>>2);
        float2 v = make_float2(tf32r(rows[slot][ch]), tf32r(rows[slot+4][ch]));
        *(float2*)(out + 8192 + (size_t)idx*2) = v;
    }
}

// ---------------------------------------------------------------------------
// P2: pack w1 (fg,bg) into B-frag images: [bank][8nt][32ks][32lane] float2
// ---------------------------------------------------------------------------
__global__ void wpack_kernel(const float* __restrict__ w1f, const float* __restrict__ w1b){
    int idx = blockIdx.x*256 + threadIdx.x;      // 0..16383
    int bank = idx >> 13, r = idx & 8191;
    int nt = r>>10, ks = (r>>5)&31, ln = r&31;
    int c = ks*8 + (ln&3), hcol = nt*8 + (ln>>2);
    const float* w = bank ? w1b : w1f;
    float2 v = make_float2(tf32r(w[c*CHID + hcol]), tf32r(w[(c+4)*CHID + hcol]));
    ((float2*)g_wf)[idx] = v;
}

// ---------------------------------------------------------------------------
// P3: feats -> g_xn (fp32) + g_qf (frag-major tf32). One block per 64 pixels.
// ---------------------------------------------------------------------------
__global__ void xn_kernel(const float* __restrict__ feats){
    extern __shared__ float xr[];               // [64][260]
    __shared__ float part[4][64];
    __shared__ float sinv[64];
    int bh = blockIdx.x, b = bh >> 6, h = bh & 63;
    int tid = threadIdx.x;
    int w = tid & 63, cg = tid >> 6;
    float ps = 0.f;
    for (int c = cg; c < CC; c += 4){
        float v = feats[(((size_t)b*CC + c)*64 + h)*64 + w];
        ps = fmaf(v, v, ps);
    }
    part[cg][w] = ps;
    __syncthreads();
    if (tid < 64){
        float s = part[0][tid] + part[1][tid] + part[2][tid] + part[3][tid];
        sinv[tid] = 1.0f / fmaxf(sqrtf(s), 1e-12f);
    }
    __syncthreads();
    int nbase = bh * 64;
    for (int i = tid; i < CC*64; i += 256){
        int ww = i >> 8, c = i & 255;
        float v = feats[(((size_t)b*CC + c)*64 + h)*64 + ww] * sinv[ww];
        g_xn[(size_t)(nbase + ww)*CC + c] = v;
        xr[ww*260 + c] = v;
    }
    __syncthreads();
    float4* out = (float4*)(g_qf + (size_t)bh * 16384);
    for (int idx = tid; idx < 4096; idx += 256){
        int mt = idx>>10, ks = (idx>>5)&31, ln = idx&31;
        int m = mt*16 + (ln>>2), k = ks*8 + (ln&3);
        float4 v;
        v.x = tf32r(xr[m*260 + k]);
        v.y = tf32r(xr[(m+8)*260 + k]);
        v.z = tf32r(xr[m*260 + k + 4]);
        v.w = tf32r(xr[(m+8)*260 + k + 4]);
        out[idx] = v;
    }
}

// ---------------------------------------------------------------------------
// P4: gate MLPs via mma. CTA = 64 pixels; warp w: mt=w&3, bank=w>>2.
// A-frags LDG from g_qf, B-frags LDG from g_wf (L1-resident).
// ---------------------------------------------------------------------------
__global__ __launch_bounds__(256) void gate_kernel(
    const float* __restrict__ b1f, const float* __restrict__ w2f, const float* __restrict__ b2f,
    const float* __restrict__ b1b, const float* __restrict__ w2b, const float* __restrict__ b2b){
    int cta = blockIdx.x, tid = threadIdx.x, wid = tid>>5, lane = tid&31;
    int mt = wid & 3, bank = wid >> 2;
    const uint4* A = (const uint4*)g_qf + (size_t)cta*4096 + mt*1024 + lane;
    const uint2* B = (const uint2*)g_wf + bank*8192 + lane;

    float acc[8][4];
    #pragma unroll
    for (int nt = 0; nt < 8; nt++)
        acc[nt][0] = acc[nt][1] = acc[nt][2] = acc[nt][3] = 0.f;

    #pragma unroll 4
    for (int ks = 0; ks < 32; ks++){
        uint4 a = A[ks*32];
        #pragma unroll
        for (int nt = 0; nt < 8; nt++)
            mma8(acc[nt], a, B[nt*1024 + ks*32]);
    }

    const float* b1 = bank ? b1b : b1f;
    const float* w2 = bank ? w2b : w2f;
    float bias2 = bank ? b2b[0] : b2f[0];
    float sA = 0.f, sB = 0.f;
    #pragma unroll
    for (int nt = 0; nt < 8; nt++){
        #pragma unroll
        for (int c = 0; c < 4; c++){
            int col = nt*8 + 2*(lane&3) + (c&1);
            float hv = fmaxf(acc[nt][c] + b1[col], 0.f) * w2[col];
            if (c < 2) sA += hv; else sB += hv;
        }
    }
    sA += __shfl_xor_sync(0xffffffffu, sA, 1);
    sA += __shfl_xor_sync(0xffffffffu, sA, 2);
    sB += __shfl_xor_sync(0xffffffffu, sB, 1);
    sB += __shfl_xor_sync(0xffffffffu, sB, 2);
    if ((lane & 3) == 0){
        int rA = cta*64 + mt*16 + (lane>>2);
        float* dst = bank ? g_gbg : g_gfg;
        dst[rA]     = 1.0f / (1.0f + __expf(-(sA + bias2)));
        dst[rA + 8] = 1.0f / (1.0f + __expf(-(sB + bias2)));
    }
}

// ---------------------------------------------------------------------------
// P5: fused dual attention via mma.sync tf32, restructured for smem-BW.
// 256 thr = 8 warps.
// GEMM1 (warps 0-3): warp (mtg=w&1, ntg=w>>1&1) computes 2mt x 2nt x 32ks.
// GEMM2 (all 8):     warp (mtg=w&1, nto=w>>1)  computes 2mt x 8nt x 4ks.
// ---------------------------------------------------------------------------
__global__ __launch_bounds__(256, 1) void attn_kernel(float* __restrict__ out){
    extern __shared__ __align__(16) char sm[];
    __shared__ __align__(8) unsigned long long barsm[3];

    const int tid = threadIdx.x, wid = tid >> 5, lane = tid & 31;
    const int cta = blockIdx.x;
    const int mtg = wid & 1;
    const int ntg = (wid >> 1) & 1;
    const int nto = wid >> 1;
    const bool swarp = (wid < 4);

    const uint32_t smb = s2u(sm);
    float* QFf = (float*)(sm + QF_OFF);
    float* PF  = (float*)(sm + PF_OFF);
    float* LSM = (float*)(sm + LSM_OFF);
    const uint32_t qbar = s2u(barsm);
    const uint32_t fbar0 = qbar + 8, fbar1 = qbar + 16;

    if (tid == 0){ mbar_init(qbar,1); mbar_init(fbar0,1); mbar_init(fbar1,1); }
    if (tid < 128) LSM[tid] = 0.f;
    __syncthreads();
    if (tid == 0){
        mbar_tx(qbar, 65536);
        bulk_g2s(smb + QF_OFF, g_qf + (size_t)cta*16384, 65536, qbar);
        mbar_tx(fbar0, TB_SZ);
        bulk_g2s(smb + TB_OFF, g_timg, TB_SZ, fbar0);
        mbar_tx(fbar1, TB_SZ);
        bulk_g2s(smb + TB_OFF + TB_SZ, g_timg + 16384, TB_SZ, fbar1);
    }
    mbar_wait(qbar, 0);

    for (int pass = 0; pass < 2; pass++){
        float accO[2][8][4];
        #pragma unroll
        for (int i = 0; i < 2; i++)
            #pragma unroll
            for (int j = 0; j < 8; j++)
                accO[i][j][0] = accO[i][j][1] = accO[i][j][2] = accO[i][j][3] = 0.f;
        float l4[4] = {0.f, 0.f, 0.f, 0.f};

        for (int tt = 0; tt < NTILE; tt++){
            const int t = pass*NTILE + tt;
            const int buf = t & 1;
            float* TB = (float*)(sm + TB_OFF + buf*TB_SZ);
            mbar_wait(buf ? fbar1 : fbar0, (t >> 1) & 1);

            if (swarp){
                // ---- GEMM1: 2mt x 2nt x 32ks ----
                float accS[2][2][4];
                #pragma unroll
                for (int i = 0; i < 2; i++)
                    #pragma unroll
                    for (int j = 0; j < 2; j++)
                        accS[i][j][0] = accS[i][j][1] = accS[i][j][2] = accS[i][j][3] = 0.f;
                const uint4* Aq = (const uint4*)QFf + lane;
                const uint2* Bq = (const uint2*)TB + lane;
                #pragma unroll 4
                for (int ks = 0; ks < 32; ks++){
                    uint4 a0 = Aq[(2*mtg)*1024   + ks*32];
                    uint4 a1 = Aq[(2*mtg+1)*1024 + ks*32];
                    uint2 b0 = Bq[(2*ntg)*1024   + ks*32];
                    uint2 b1 = Bq[(2*ntg+1)*1024 + ks*32];
                    mma8(accS[0][0], a0, b0); mma8(accS[0][1], a0, b1);
                    mma8(accS[1][0], a1, b0); mma8(accS[1][1], a1, b1);
                }
                // ---- S epilogue: exp, mask, lsum, PF (A-frag layout) ----
                #pragma unroll
                for (int i = 0; i < 2; i++){
                    const int mtA = 2*mtg + i;
                    #pragma unroll
                    for (int j = 0; j < 2; j++){
                        const int nt = 2*ntg + j;
                        const bool maskf = (tt == NTILE-1) && (nt > 0);
                        #pragma unroll
                        for (int c = 0; c < 4; c++){
                            float p = __expf(accS[i][j][c] * INV_TEMP);
                            if (maskf) p = 0.f;
                            p = tf32r(p);
                            l4[i*2 + (c>>1)] += p;
                            int colin = 2*(lane & 3) + (c & 1);
                            int comp  = ((colin >= 4) ? 2 : 0) + ((c >> 1) & 1);
                            int tp    = (lane & ~3) | (colin & 3);
                            PF[((mtA*4 + nt)*32 + tp)*4 + comp] = p;
                        }
                    }
                }
            }
            __syncthreads();

            // ---- GEMM2: 2mt x 8nt x 4ks ----
            {
                const uint2* B2 = (const uint2*)(TB + 8192) + lane;
                const uint4* Ap = (const uint4*)PF + lane;
                #pragma unroll
                for (int ks2 = 0; ks2 < 4; ks2++){
                    uint4 a0 = Ap[((2*mtg)*4   + ks2)*32];
                    uint4 a1 = Ap[((2*mtg+1)*4 + ks2)*32];
                    #pragma unroll
                    for (int j = 0; j < 8; j++){
                        uint2 b = B2[((nto*8 + j)*4 + ks2)*32];
                        mma8(accO[0][j], a0, b);
                        mma8(accO[1][j], a1, b);
                    }
                }
            }
            __syncthreads();

            if (tid == 0 && t + 2 < NTT){
                uint32_t fb = buf ? fbar1 : fbar0;
                mbar_tx(fb, TB_SZ);
                bulk_g2s(smb + TB_OFF + buf*TB_SZ, g_timg + (size_t)(t+2)*16384, TB_SZ, fb);
            }
        }

        // ---- lsum reduction (S-warps) ----
        if (swarp){
            #pragma unroll
            for (int q = 0; q < 4; q++){
                float v = l4[q];
                v += __shfl_xor_sync(0xffffffffu, v, 1);
                v += __shfl_xor_sync(0xffffffffu, v, 2);
                if ((lane & 3) == 0)
                    atomicAdd(&LSM[pass*64 + (2*mtg + (q>>1))*16 + (lane>>2) + 8*(q&1)], v);
            }
        }
        __syncthreads();

        // ---- output epilogue ----
        #pragma unroll
        for (int i = 0; i < 2; i++){
            const int mtA = 2*mtg + i;
            const int r0 = mtA*16 + (lane>>2);
            const int nA = cta*64 + r0, nB = nA + 8;
            const float gA = pass ? g_gbg[nA] : g_gfg[nA];
            const float gB = pass ? g_gbg[nB] : g_gfg[nB];
            const float cA = gA / LSM[pass*64 + r0];
            const float cB = gB / LSM[pass*64 + r0 + 8];
            const size_t baseA = ((size_t)(nA >> 12) * CC) * 4096 + (nA & 4095);
            const size_t baseB = baseA + 8;
            const float* xnA = g_xn + (size_t)nA*CC;
            const float* xnB = g_xn + (size_t)nB*CC;
            #pragma unroll
            for (int j = 0; j < 8; j++){
                int c0 = (nto*8 + j)*8 + 2*(lane & 3);
                size_t aA = baseA + (size_t)c0*4096;
                size_t aB = baseB + (size_t)c0*4096;
                if (pass == 0){
                    out[aA]        = xnA[c0]   + cA*accO[i][j][0];
                    out[aA + 4096] = xnA[c0+1] + cA*accO[i][j][1];
                    out[aB]        = xnB[c0]   + cB*accO[i][j][2];
                    out[aB + 4096] = xnB[c0+1] + cB*accO[i][j][3];
                } else {
                    out[aA]        -= cA*accO[i][j][0];
                    out[aA + 4096] -= cA*accO[i][j][1];
                    out[aB]        -= cB*accO[i][j][2];
                    out[aB + 4096] -= cB*accO[i][j][3];
                }
            }
        }
    }
}

// ---------------------------------------------------------------------------
extern "C" void kernel_launch(void* const* d_in, const int* in_sizes, int n_in,
                              void* d_out, int out_size){
    const float* feats = (const float*)d_in[0];
    const float* fgm   = (const float*)d_in[1];
    const float* bgm   = (const float*)d_in[2];
    const float* w1f   = (const float*)d_in[3];
    const float* b1f   = (const float*)d_in[4];
    const float* w2f   = (const float*)d_in[5];
    const float* b2f   = (const float*)d_in[6];
    const float* w1b   = (const float*)d_in[7];
    const float* b1b   = (const float*)d_in[8];
    const float* w2b   = (const float*)d_in[9];
    const float* b2b   = (const float*)d_in[10];
    float* out = (float*)d_out;

    cudaFuncSetAttribute(attn_kernel, cudaFuncAttributeMaxDynamicSharedMemorySize, SMEM_DYN);
    cudaFuncSetAttribute(xn_kernel, cudaFuncAttributeMaxDynamicSharedMemorySize, XN_SMEM);

    pack_mem_kernel<<<128, 256>>>(fgm, bgm);
    wpack_kernel<<<64, 256>>>(w1f, w1b);
    xn_kernel<<<512, 256, XN_SMEM>>>(feats);
    gate_kernel<<<512, 256>>>(b1f, w2f, b2f, b1b, w2b, b2b);
    attn_kernel<<<NPIX / PT, 256, SMEM_DYN>>>(out);
}

// round 9
// speedup vs baseline: 10.0346x; 1.6259x over previous
#include <cuda_runtime.h>
#include <cuda_fp16.h>
#include <cstdint>

#define CC   256
#define MM   2024
#define NPIX 32768
#define CHID 64
#define PT   64
#define KT   32
#define NTILE 64          // tiles per bank
#define NTT  128          // total (fg+bg)
#define INV_TEMP (1.0f/0.03f)

// dynamic smem byte offsets (attn)
#define QF_OFF   0        // 32768: Q fp16 fragments
#define TB_OFF   32768    // 2 x 32768: tile buffers (T1F 16KB + T2F 16KB each)
#define TB_SZ    32768
#define PF_OFF   98304    // 5120: P fp16 pairs [64 rows][20 uint stride]
#define ALPH_OFF 103424   // 256: per-row alpha
#define LROW_OFF 103680   // 256: per-row l
#define SMEM_DYN 103936

#define XN_SMEM (64*260*4)

// ---------------- global scratch ----------------
__device__ float g_xn[(size_t)NPIX*CC];
__device__ float g_gfg[NPIX];
__device__ float g_gbg[NPIX];
__device__ __align__(16) uint4 g_qf[(size_t)(NPIX/PT)*2048];   // fp16 A-frags, 32KB/CTA
__device__ __align__(16) uint2 g_timg[(size_t)NTT*4096];       // 128 tiles * 32KB
__device__ __align__(16) uint2 g_wf[8192];                     // w1 fp16 B-frags (fg+bg)

// ---------------- helpers ----------------
__device__ __forceinline__ uint32_t s2u(const void* p){
    uint32_t a;
    asm("{ .reg .u64 t; cvta.to.shared.u64 t, %1; cvt.u32.u64 %0, t; }" : "=r"(a) : "l"(p));
    return a;
}
__device__ __forceinline__ uint32_t ph2(float x, float y){
    __half2 h = __floats2half2_rn(x, y);
    return *(uint32_t*)&h;
}
__device__ __forceinline__ void mbar_init(uint32_t m, uint32_t c){
    asm volatile("mbarrier.init.shared.b64 [%0], %1;" :: "r"(m), "r"(c) : "memory");
}
__device__ __forceinline__ void mbar_tx(uint32_t m, uint32_t b){
    asm volatile("mbarrier.arrive.expect_tx.shared.b64 _, [%0], %1;" :: "r"(m), "r"(b) : "memory");
}
__device__ __forceinline__ void mbar_wait(uint32_t m, uint32_t ph){
    asm volatile(
        "{\n\t.reg .pred P;\n\t"
        "W_%=:\n\t"
        "mbarrier.try_wait.parity.acquire.cta.shared::cta.b64 P, [%0], %1, 0x989680;\n\t"
        "@P bra D_%=;\n\tbra W_%=;\n\tD_%=:\n\t}"
        :: "r"(m), "r"(ph) : "memory");
}
__device__ __forceinline__ void bulk_g2s(uint32_t dst, const void* src, uint32_t bytes, uint32_t mbar){
    asm volatile("cp.async.bulk.shared::cluster.global.mbarrier::complete_tx::bytes [%0], [%1], %2, [%3];"
        :: "r"(dst), "l"(src), "r"(bytes), "r"(mbar) : "memory");
}
// m16n8k16 fp16 mma, fp32 accum, D=C in place
__device__ __forceinline__ void mma16(float* d, uint4 a, uint2 b){
    asm volatile("mma.sync.aligned.m16n8k16.row.col.f32.f16.f16.f32 "
        "{%0,%1,%2,%3}, {%4,%5,%6,%7}, {%8,%9}, {%0,%1,%2,%3};"
        : "+f"(d[0]), "+f"(d[1]), "+f"(d[2]), "+f"(d[3])
        : "r"(a.x), "r"(a.y), "r"(a.z), "r"(a.w), "r"(b.x), "r"(b.y));
}

// ---------------------------------------------------------------------------
// P1: normalize memory rows -> fp16 frag-major tile images.
// T1F (GEMM1 B, k=channel, *INV_TEMP): [4nt][16ks][32lane] uint2 (16KB)
// T2F (GEMM2 B, k=slot):               [32nt][2ks][32lane]  uint2 (16KB)
// ---------------------------------------------------------------------------
__global__ void pack_mem_kernel(const float* __restrict__ fg, const float* __restrict__ bg){
    __shared__ float rows[KT][CC+4];
    int blk = blockIdx.x;                 // 0..127
    int bank = blk >> 6, tin = blk & 63;
    const float* src = bank ? bg : fg;
    int tid = threadIdx.x, wid = tid>>5, lane = tid&31;

    #pragma unroll
    for (int i = 0; i < 4; i++){
        int r = wid*4 + i;
        int slot = tin*KT + r;
        float4 v0 = make_float4(0.f,0.f,0.f,0.f), v1 = v0;
        if (slot < MM){
            const float4* s4 = (const float4*)(src + (size_t)slot*CC);
            v0 = s4[lane]; v1 = s4[lane+32];
            float ss = v0.x*v0.x+v0.y*v0.y+v0.z*v0.z+v0.w*v0.w
                     + v1.x*v1.x+v1.y*v1.y+v1.z*v1.z+v1.w*v1.w;
            #pragma unroll
            for (int o = 16; o; o >>= 1) ss += __shfl_xor_sync(0xffffffffu, ss, o);
            float inv = 1.0f / fmaxf(sqrtf(ss), 1e-12f);
            v0.x*=inv; v0.y*=inv; v0.z*=inv; v0.w*=inv;
            v1.x*=inv; v1.y*=inv; v1.z*=inv; v1.w*=inv;
        }
        float4* d = (float4*)&rows[r][0];
        d[lane] = v0; d[lane+32] = v1;
    }
    __syncthreads();

    uint2* out = g_timg + (size_t)blk * 4096;
    // T1F: 2048 uint2
    for (int idx = tid; idx < 2048; idx += 256){
        int nt = idx>>9, ks = (idx>>5)&15, l = idx&31;
        int g = l>>2, t = l&3;
        int slot = nt*8 + g, c = ks*16 + 2*t;
        uint2 v;
        v.x = ph2(rows[slot][c]   * INV_TEMP, rows[slot][c+1] * INV_TEMP);
        v.y = ph2(rows[slot][c+8] * INV_TEMP, rows[slot][c+9] * INV_TEMP);
        out[idx] = v;
    }
    // T2F: 2048 uint2
    for (int idx = tid; idx < 2048; idx += 256){
        int nt2 = idx>>6, ks2 = (idx>>5)&1, l = idx&31;
        int g = l>>2, t = l&3;
        int ch = nt2*8 + g, s0 = ks2*16 + 2*t;
        uint2 v;
        v.x = ph2(rows[s0][ch],   rows[s0+1][ch]);
        v.y = ph2(rows[s0+8][ch], rows[s0+9][ch]);
        out[2048 + idx] = v;
    }
}

// ---------------------------------------------------------------------------
// P2: pack w1 (fg,bg) fp16 B-frags: [bank][8nt][16ks][32lane] uint2
// ---------------------------------------------------------------------------
__global__ void wpack_kernel(const float* __restrict__ w1f, const float* __restrict__ w1b){
    int idx = blockIdx.x*256 + threadIdx.x;      // 0..8191
    int bank = idx >> 12, r = idx & 4095;
    int nt = r>>9, ks = (r>>5)&15, l = r&31;
    int g = l>>2, t = l&3;
    int hcol = nt*8 + g, c = ks*16 + 2*t;
    const float* w = bank ? w1b : w1f;
    uint2 v;
    v.x = ph2(w[c*CHID + hcol],     w[(c+1)*CHID + hcol]);
    v.y = ph2(w[(c+8)*CHID + hcol], w[(c+9)*CHID + hcol]);
    g_wf[idx] = v;
}

// ---------------------------------------------------------------------------
// P3: feats -> g_xn (fp32) + g_qf (fp16 A-frags). One block per 64 pixels.
// ---------------------------------------------------------------------------
__global__ void xn_kernel(const float* __restrict__ feats){
    extern __shared__ float xr[];               // [64][260]
    __shared__ float part[4][64];
    __shared__ float sinv[64];
    int bh = blockIdx.x, b = bh >> 6, h = bh & 63;
    int tid = threadIdx.x;
    int w = tid & 63, cg = tid >> 6;
    float ps = 0.f;
    for (int c = cg; c < CC; c += 4){
        float v = feats[(((size_t)b*CC + c)*64 + h)*64 + w];
        ps = fmaf(v, v, ps);
    }
    part[cg][w] = ps;
    __syncthreads();
    if (tid < 64){
        float s = part[0][tid] + part[1][tid] + part[2][tid] + part[3][tid];
        sinv[tid] = 1.0f / fmaxf(sqrtf(s), 1e-12f);
    }
    __syncthreads();
    int nbase = bh * 64;
    for (int i = tid; i < CC*64; i += 256){
        int ww = i >> 8, c = i & 255;
        float v = feats[(((size_t)b*CC + c)*64 + h)*64 + ww] * sinv[ww];
        g_xn[(size_t)(nbase + ww)*CC + c] = v;
        xr[ww*260 + c] = v;
    }
    __syncthreads();
    uint4* out = g_qf + (size_t)bh * 2048;
    for (int idx = tid; idx < 2048; idx += 256){
        int mt = idx>>9, ks = (idx>>5)&15, l = idx&31;
        int g = l>>2, t = l&3;
        int m = mt*16 + g, k = ks*16 + 2*t;
        uint4 v;
        v.x = ph2(xr[m*260 + k],       xr[m*260 + k+1]);
        v.y = ph2(xr[(m+8)*260 + k],   xr[(m+8)*260 + k+1]);
        v.z = ph2(xr[m*260 + k+8],     xr[m*260 + k+9]);
        v.w = ph2(xr[(m+8)*260 + k+8], xr[(m+8)*260 + k+9]);
        out[idx] = v;
    }
}

// ---------------------------------------------------------------------------
// P4: gate MLPs via fp16 mma. CTA = 64 px; warp: mt=w&3, bank=w>>2.
// ---------------------------------------------------------------------------
__global__ __launch_bounds__(256) void gate_kernel(
    const float* __restrict__ b1f, const float* __restrict__ w2f, const float* __restrict__ b2f,
    const float* __restrict__ b1b, const float* __restrict__ w2b, const float* __restrict__ b2b){
    int cta = blockIdx.x, tid = threadIdx.x, wid = tid>>5, lane = tid&31;
    int mt = wid & 3, bank = wid >> 2;
    const uint4* A = g_qf + (size_t)cta*2048 + mt*512 + lane;
    const uint2* B = g_wf + bank*4096 + lane;

    float acc[8][4];
    #pragma unroll
    for (int nt = 0; nt < 8; nt++)
        acc[nt][0] = acc[nt][1] = acc[nt][2] = acc[nt][3] = 0.f;

    #pragma unroll 4
    for (int ks = 0; ks < 16; ks++){
        uint4 a = A[ks*32];
        #pragma unroll
        for (int nt = 0; nt < 8; nt++)
            mma16(acc[nt], a, B[(nt*16 + ks)*32]);
    }

    const float* b1 = bank ? b1b : b1f;
    const float* w2 = bank ? w2b : w2f;
    float bias2 = bank ? b2b[0] : b2f[0];
    float sA = 0.f, sB = 0.f;
    #pragma unroll
    for (int nt = 0; nt < 8; nt++){
        #pragma unroll
        for (int c = 0; c < 4; c++){
            int col = nt*8 + 2*(lane&3) + (c&1);
            float hv = fmaxf(acc[nt][c] + b1[col], 0.f) * w2[col];
            if (c < 2) sA += hv; else sB += hv;
        }
    }
    sA += __shfl_xor_sync(0xffffffffu, sA, 1);
    sA += __shfl_xor_sync(0xffffffffu, sA, 2);
    sB += __shfl_xor_sync(0xffffffffu, sB, 1);
    sB += __shfl_xor_sync(0xffffffffu, sB, 2);
    if ((lane & 3) == 0){
        int rA = cta*64 + mt*16 + (lane>>2);
        float* dst = bank ? g_gbg : g_gfg;
        dst[rA]     = 1.0f / (1.0f + __expf(-(sA + bias2)));
        dst[rA + 8] = 1.0f / (1.0f + __expf(-(sB + bias2)));
    }
}

// ---------------------------------------------------------------------------
// P5: fused dual flash attention, fp16 mma, online softmax.
// 8 warps. GEMM1: warps 0-3, warp w = 1mt(w) x 4nt x 16ks (rows warp-local).
// GEMM2: all 8 warps: (mtg=w&1 -> 2mt, nto=w>>1 -> 8nt) x 2ks16.
// ---------------------------------------------------------------------------
__global__ __launch_bounds__(256, 2) void attn_kernel(float* __restrict__ out){
    extern __shared__ __align__(16) char sm[];
    __shared__ __align__(8) unsigned long long barsm[3];

    const int tid = threadIdx.x, wid = tid >> 5, lane = tid & 31;
    const int g = lane >> 2, t = lane & 3;
    const int cta = blockIdx.x;
    const int mtg = wid & 1;
    const int nto = wid >> 1;
    const bool swarp = (wid < 4);

    const uint32_t smb = s2u(sm);
    const uint4* QF4 = (const uint4*)(sm + QF_OFF);
    uint32_t* PFu   = (uint32_t*)(sm + PF_OFF);
    float* ALPH     = (float*)(sm + ALPH_OFF);
    float* LROW     = (float*)(sm + LROW_OFF);
    const uint32_t qbar = s2u(barsm);
    const uint32_t fbar0 = qbar + 8, fbar1 = qbar + 16;

    if (tid == 0){ mbar_init(qbar,1); mbar_init(fbar0,1); mbar_init(fbar1,1); }
    __syncthreads();
    if (tid == 0){
        mbar_tx(qbar, 32768);
        bulk_g2s(smb + QF_OFF, g_qf + (size_t)cta*2048, 32768, qbar);
        mbar_tx(fbar0, TB_SZ);
        bulk_g2s(smb + TB_OFF, g_timg, TB_SZ, fbar0);
        mbar_tx(fbar1, TB_SZ);
        bulk_g2s(smb + TB_OFF + TB_SZ, g_timg + 4096, TB_SZ, fbar1);
    }
    mbar_wait(qbar, 0);

    const int rS  = wid*16 + g;          // S-warp rows rS, rS+8
    const int rO0 = 2*mtg*16, rO1 = rO0 + 16;

    for (int pass = 0; pass < 2; pass++){
        float accO[2][8][4];
        #pragma unroll
        for (int i = 0; i < 2; i++)
            #pragma unroll
            for (int j = 0; j < 8; j++)
                accO[i][j][0] = accO[i][j][1] = accO[i][j][2] = accO[i][j][3] = 0.f;
        float mA = -1e30f, mB = -1e30f, lA = 0.f, lB = 0.f;

        for (int tt = 0; tt < NTILE; tt++){
            const int tgl = pass*NTILE + tt;
            const int buf = tgl & 1;
            char* TB = sm + TB_OFF + buf*TB_SZ;
            mbar_wait(buf ? fbar1 : fbar0, (tgl >> 1) & 1);

            if (swarp){
                // ---- GEMM1: 1mt x 4nt x 16ks ----
                float accS[4][4];
                #pragma unroll
                for (int j = 0; j < 4; j++)
                    accS[j][0] = accS[j][1] = accS[j][2] = accS[j][3] = 0.f;
                const uint4* Aq = QF4 + wid*512 + lane;
                const uint2* Bq = (const uint2*)TB + lane;
                #pragma unroll 4
                for (int ks = 0; ks < 16; ks++){
                    uint4 a = Aq[ks*32];
                    mma16(accS[0], a, Bq[(ks     )*32]);
                    mma16(accS[1], a, Bq[(ks+ 16)*32]);
                    mma16(accS[2], a, Bq[(ks+ 32)*32]);
                    mma16(accS[3], a, Bq[(ks+ 48)*32]);
                }
                if (tt == NTILE-1){
                    #pragma unroll
                    for (int j = 1; j < 4; j++)
                        accS[j][0] = accS[j][1] = accS[j][2] = accS[j][3] = -1e30f;
                }
                // ---- row stats (warp-local) ----
                float mAt = -1e30f, mBt = -1e30f;
                #pragma unroll
                for (int j = 0; j < 4; j++){
                    mAt = fmaxf(mAt, fmaxf(accS[j][0], accS[j][1]));
                    mBt = fmaxf(mBt, fmaxf(accS[j][2], accS[j][3]));
                }
                mAt = fmaxf(mAt, __shfl_xor_sync(0xffffffffu, mAt, 1));
                mAt = fmaxf(mAt, __shfl_xor_sync(0xffffffffu, mAt, 2));
                mBt = fmaxf(mBt, __shfl_xor_sync(0xffffffffu, mBt, 1));
                mBt = fmaxf(mBt, __shfl_xor_sync(0xffffffffu, mBt, 2));
                float mnA = fmaxf(mA, mAt), mnB = fmaxf(mB, mBt);
                float alA = __expf(mA - mnA), alB = __expf(mB - mnB);
                float lAt = 0.f, lBt = 0.f;
                #pragma unroll
                for (int j = 0; j < 4; j++){
                    float p0 = __expf(accS[j][0] - mnA);
                    float p1 = __expf(accS[j][1] - mnA);
                    float p2 = __expf(accS[j][2] - mnB);
                    float p3 = __expf(accS[j][3] - mnB);
                    lAt += p0 + p1; lBt += p2 + p3;
                    PFu[rS*20     + j*4 + t] = ph2(p0, p1);
                    PFu[(rS+8)*20 + j*4 + t] = ph2(p2, p3);
                }
                lAt += __shfl_xor_sync(0xffffffffu, lAt, 1);
                lAt += __shfl_xor_sync(0xffffffffu, lAt, 2);
                lBt += __shfl_xor_sync(0xffffffffu, lBt, 1);
                lBt += __shfl_xor_sync(0xffffffffu, lBt, 2);
                lA = lA*alA + lAt; lB = lB*alB + lBt;
                mA = mnA; mB = mnB;
                if (t == 0){ ALPH[rS] = alA; ALPH[rS+8] = alB; }
            }
            __syncthreads();

            // ---- rescale accO by alpha ----
            {
                float aA0 = ALPH[rO0 + g], aB0 = ALPH[rO0 + 8 + g];
                float aA1 = ALPH[rO1 + g], aB1 = ALPH[rO1 + 8 + g];
                #pragma unroll
                for (int j = 0; j < 8; j++){
                    accO[0][j][0] *= aA0; accO[0][j][1] *= aA0;
                    accO[0][j][2] *= aB0; accO[0][j][3] *= aB0;
                    accO[1][j][0] *= aA1; accO[1][j][1] *= aA1;
                    accO[1][j][2] *= aB1; accO[1][j][3] *= aB1;
                }
            }

            // ---- GEMM2: 2mt x 8nt x 2ks ----
            {
                const uint2* B2 = (const uint2*)(TB + 16384) + lane;
                #pragma unroll
                for (int ks2 = 0; ks2 < 2; ks2++){
                    uint4 a0, a1;
                    a0.x = PFu[(rO0+g)*20   + ks2*8 + t];
                    a0.y = PFu[(rO0+8+g)*20 + ks2*8 + t];
                    a0.z = PFu[(rO0+g)*20   + ks2*8 + t + 4];
                    a0.w = PFu[(rO0+8+g)*20 + ks2*8 + t + 4];
                    a1.x = PFu[(rO1+g)*20   + ks2*8 + t];
                    a1.y = PFu[(rO1+8+g)*20 + ks2*8 + t];
                    a1.z = PFu[(rO1+g)*20   + ks2*8 + t + 4];
                    a1.w = PFu[(rO1+8+g)*20 + ks2*8 + t + 4];
                    #pragma unroll
                    for (int j = 0; j < 8; j++){
                        uint2 b = B2[((nto*8 + j)*2 + ks2)*32];
                        mma16(accO[0][j], a0, b);
                        mma16(accO[1][j], a1, b);
                    }
                }
            }
            __syncthreads();

            if (tid == 0 && tgl + 2 < NTT){
                uint32_t fb = buf ? fbar1 : fbar0;
                mbar_tx(fb, TB_SZ);
                bulk_g2s(smb + TB_OFF + buf*TB_SZ, g_timg + (size_t)(tgl+2)*4096, TB_SZ, fb);
            }
        }

        // ---- pass epilogue ----
        if (swarp && t == 0){ LROW[rS] = lA; LROW[rS+8] = lB; }
        __syncthreads();

        #pragma unroll
        for (int i = 0; i < 2; i++){
            const int r0 = (2*mtg + i)*16 + g;
            const int nA = cta*64 + r0, nB = nA + 8;
            const float gA = pass ? g_gbg[nA] : g_gfg[nA];
            const float gB = pass ? g_gbg[nB] : g_gfg[nB];
            const float cA = gA / LROW[r0];
            const float cB = gB / LROW[r0 + 8];
            const size_t baseA = ((size_t)(nA >> 12) * CC) * 4096 + (nA & 4095);
            const size_t baseB = baseA + 8;
            const float* xnA = g_xn + (size_t)nA*CC;
            const float* xnB = g_xn + (size_t)nB*CC;
            #pragma unroll
            for (int j = 0; j < 8; j++){
                int c0 = (nto*8 + j)*8 + 2*t;
                size_t aA = baseA + (size_t)c0*4096;
                size_t aB = baseB + (size_t)c0*4096;
                if (pass == 0){
                    out[aA]        = xnA[c0]   + cA*accO[i][j][0];
                    out[aA + 4096] = xnA[c0+1] + cA*accO[i][j][1];
                    out[aB]        = xnB[c0]   + cB*accO[i][j][2];
                    out[aB + 4096] = xnB[c0+1] + cB*accO[i][j][3];
                } else {
                    out[aA]        -= cA*accO[i][j][0];
                    out[aA + 4096] -= cA*accO[i][j][1];
                    out[aB]        -= cB*accO[i][j][2];
                    out[aB + 4096] -= cB*accO[i][j][3];
                }
            }
        }
        __syncthreads();
    }
}

// ---------------------------------------------------------------------------
extern "C" void kernel_launch(void* const* d_in, const int* in_sizes, int n_in,
                              void* d_out, int out_size){
    const float* feats = (const float*)d_in[0];
    const float* fgm   = (const float*)d_in[1];
    const float* bgm   = (const float*)d_in[2];
    const float* w1f   = (const float*)d_in[3];
    const float* b1f   = (const float*)d_in[4];
    const float* w2f   = (const float*)d_in[5];
    const float* b2f   = (const float*)d_in[6];
    const float* w1b   = (const float*)d_in[7];
    const float* b1b   = (const float*)d_in[8];
    const float* w2b   = (const float*)d_in[9];
    const float* b2b   = (const float*)d_in[10];
    float* out = (float*)d_out;

    cudaFuncSetAttribute(attn_kernel, cudaFuncAttributeMaxDynamicSharedMemorySize, SMEM_DYN);
    cudaFuncSetAttribute(xn_kernel, cudaFuncAttributeMaxDynamicSharedMemorySize, XN_SMEM);

    pack_mem_kernel<<<128, 256>>>(fgm, bgm);
    wpack_kernel<<<32, 256>>>(w1f, w1b);
    xn_kernel<<<512, 256, XN_SMEM>>>(feats);
    gate_kernel<<<512, 256>>>(b1f, w2f, b2f, b1b, w2b, b2b);
    attn_kernel<<<NPIX / PT, 256, SMEM_DYN>>>(out);
}